// round 15
// baseline (speedup 1.0000x reference)
#include <cuda_runtime.h>
#include <cuda_bf16.h>
#include <cuda_fp16.h>
#include <mma.h>
#include <cstdint>
#include <cstddef>

using namespace nvcuda;

#define BB 2
#define NN 2048
#define DD 1024
#define HH 16
#define DH 64
#define RR (BB*NN)
#define MM 2048
#define BIGV (1<<30)

// ---------------- scratch ----------------
__device__ float g_Yq[(size_t)RR*DD];
__device__ float g_Yk[(size_t)RR*DD];
__device__ float g_Q[(size_t)BB*HH*NN*DH];
__device__ float g_K[(size_t)BB*HH*NN*DH];
__device__ float g_S0[(size_t)BB*NN*MM];
__device__ float g_Fi[BB*MM];
__device__ int   g_ev[BB*MM];
__device__ __half g_hXa[(size_t)RR*DD], g_hXb[(size_t)RR*DD];
__device__ __half g_hWqa[(size_t)DD*DD], g_hWqb[(size_t)DD*DD];
__device__ __half g_hWka[(size_t)DD*DD], g_hWkb[(size_t)DD*DD];
__device__ __half g_hWva[(size_t)DD*DD], g_hWvb[(size_t)DD*DD];
__device__ __half g_hWoa[(size_t)DD*DD], g_hWob[(size_t)DD*DD];
__device__ __half g_hAa[(size_t)RR*DD], g_hAb[(size_t)RR*DD];
__device__ __nv_bfloat16 g_Qh[(size_t)BB*HH*NN*DH], g_Qm[(size_t)BB*HH*NN*DH];
__device__ __nv_bfloat16 g_Kh[(size_t)BB*HH*NN*DH], g_Km[(size_t)BB*HH*NN*DH];
__device__ __nv_bfloat16 g_Vh[(size_t)BB*HH*NN*DH], g_Vm[(size_t)BB*HH*NN*DH];

// fast exp on FMA pipe (no MUFU)
__device__ __forceinline__ float fexp(float x) {
    float t = x * 1.4426950408889634f;
    int ei = __float2int_rn(t);
    float f = t - (float)ei;
    float p = 1.3333558146428443e-3f;
    p = fmaf(p, f, 9.6181291076284772e-3f);
    p = fmaf(p, f, 5.5504108664821580e-2f);
    p = fmaf(p, f, 2.4022650695910072e-1f);
    p = fmaf(p, f, 6.9314718055994531e-1f);
    p = fmaf(p, f, 1.0f);
    return __int_as_float(__float_as_int(p) + (ei << 23));
}

__device__ __forceinline__ uint32_t cvta_s(const void* p) {
    uint32_t a;
    asm("{ .reg .u64 t; cvta.to.shared.u64 t, %1; cvt.u32.u64 %0, t; }" : "=r"(a) : "l"(p));
    return a;
}
#define LDSM_X4(r0,r1,r2,r3,a) \
    asm volatile("ldmatrix.sync.aligned.m8n8.x4.shared.b16 {%0,%1,%2,%3}, [%4];" \
        : "=r"(r0),"=r"(r1),"=r"(r2),"=r"(r3) : "r"(a))
#define LDSM_X2(r0,r1,a) \
    asm volatile("ldmatrix.sync.aligned.m8n8.x2.shared.b16 {%0,%1}, [%2];" \
        : "=r"(r0),"=r"(r1) : "r"(a))
#define LDSM_X2T(r0,r1,a) \
    asm volatile("ldmatrix.sync.aligned.m8n8.x2.trans.shared.b16 {%0,%1}, [%2];" \
        : "=r"(r0),"=r"(r1) : "r"(a))
#define MMA_BF16(d,a0,a1,a2,a3,b0,b1) \
    asm volatile("mma.sync.aligned.m16n8k16.row.col.f32.bf16.bf16.f32 " \
        "{%0,%1,%2,%3}, {%4,%5,%6,%7}, {%8,%9}, {%0,%1,%2,%3};" \
        : "+f"((d)[0]),"+f"((d)[1]),"+f"((d)[2]),"+f"((d)[3]) \
        : "r"(a0),"r"(a1),"r"(a2),"r"(a3),"r"(b0),"r"(b1))
#define CPASYNC16(s,g) asm volatile("cp.async.ca.shared.global [%0], [%1], 16;" :: "r"(s), "l"(g))
#define CPASYNC4(s,g)  asm volatile("cp.async.ca.shared.global [%0], [%1], 4;"  :: "r"(s), "l"(g))
#define CPCOMMIT() asm volatile("cp.async.commit_group;" ::: "memory")
#define CPWAIT0()  asm volatile("cp.async.wait_group 0;" ::: "memory")

// ---------------- conversions ----------------
__global__ void __launch_bounds__(256) conv2h_kernel(
    const float* __restrict__ X, __half* __restrict__ H, __half* __restrict__ M)
{
    int i = (blockIdx.x * 256 + threadIdx.x) * 4;
    float4 v = *(const float4*)(X + i);
    __half h0 = __float2half_rn(v.x), h1 = __float2half_rn(v.y);
    __half h2 = __float2half_rn(v.z), h3 = __float2half_rn(v.w);
    __half2 ha = __halves2half2(h0, h1), hb = __halves2half2(h2, h3);
    __half2 ma = __halves2half2(__float2half_rn(v.x - __half2float(h0)),
                                __float2half_rn(v.y - __half2float(h1)));
    __half2 mb = __halves2half2(__float2half_rn(v.z - __half2float(h2)),
                                __float2half_rn(v.w - __half2float(h3)));
    *(__half2*)(H + i) = ha; *(__half2*)(H + i + 2) = hb;
    *(__half2*)(M + i) = ma; *(__half2*)(M + i + 2) = mb;
}

// 4 weight transposes fused: blockIdx.z selects the matrix
__global__ void __launch_bounds__(256) convW4_kernel(
    const float* __restrict__ W0, const float* __restrict__ W1,
    const float* __restrict__ W2, const float* __restrict__ W3,
    __half* __restrict__ TH0, __half* __restrict__ TM0,
    __half* __restrict__ TH1, __half* __restrict__ TM1,
    __half* __restrict__ TH2, __half* __restrict__ TM2,
    __half* __restrict__ TH3, __half* __restrict__ TM3)
{
    const float* W = (blockIdx.z == 0) ? W0 : (blockIdx.z == 1) ? W1 : (blockIdx.z == 2) ? W2 : W3;
    __half* TH = (blockIdx.z == 0) ? TH0 : (blockIdx.z == 1) ? TH1 : (blockIdx.z == 2) ? TH2 : TH3;
    __half* TM = (blockIdx.z == 0) ? TM0 : (blockIdx.z == 1) ? TM1 : (blockIdx.z == 2) ? TM2 : TM3;
    __shared__ float tile[32][33];
    int n0 = blockIdx.x * 32, k0 = blockIdx.y * 32;
    int tx = threadIdx.x, ty = threadIdx.y;
#pragma unroll
    for (int i = 0; i < 32; i += 8)
        tile[ty + i][tx] = W[(size_t)(k0 + ty + i) * DD + n0 + tx];
    __syncthreads();
#pragma unroll
    for (int i = 0; i < 32; i += 8) {
        float v = tile[tx][ty + i];
        __half h = __float2half_rn(v);
        size_t o = (size_t)(n0 + ty + i) * DD + k0 + tx;
        TH[o] = h;
        TM[o] = __float2half_rn(v - __half2float(h));
    }
}

// ---------------- fp16 2-split WMMA GEMM, 128x128 tile, cp.async, 1 sync/iter ----------------
#define HLD 40
#define HPART (128*HLD)
#define HBUF (4*HPART)
#define GH_SMEM (2*HBUF*2)

__global__ void __launch_bounds__(256) gemm_h2_kernel(
    const __half* __restrict__ A0, const __half* __restrict__ A1,
    const __half* __restrict__ B0, const __half* __restrict__ B1,
    float* __restrict__ C,
    __nv_bfloat16* __restrict__ SH, __nv_bfloat16* __restrict__ SM,
    int mode)
{
    extern __shared__ __half smh[];
    uint32_t sb = cvta_s(smh);
    int tid = threadIdx.x, wid = tid >> 5;
    int wm = wid & 3, wn = wid >> 2;
    int row0 = blockIdx.y * 128, col0 = blockIdx.x * 128;

    const __half* ap[2] = { A0 + (size_t)row0 * DD, A1 + (size_t)row0 * DD };
    const __half* bp[2] = { B0 + (size_t)col0 * DD, B1 + (size_t)col0 * DD };

    int ar0 = (tid * 2) >> 2,     ac0 = ((tid * 2) & 3) * 8;
    int ar1 = (tid * 2 + 1) >> 2, ac1 = ((tid * 2 + 1) & 3) * 8;

    wmma::fragment<wmma::accumulator, 16, 16, 16, float> acc[2][4];
#pragma unroll
    for (int i = 0; i < 2; ++i)
#pragma unroll
        for (int j = 0; j < 4; ++j) wmma::fill_fragment(acc[i][j], 0.0f);

#define PREF(BUF, KB) do { \
    uint32_t _b = sb + (BUF)*HBUF*2; \
    CPASYNC16(_b + (0*HPART + ar0*HLD + ac0)*2, ap[0] + (size_t)ar0*DD + (KB) + ac0); \
    CPASYNC16(_b + (0*HPART + ar1*HLD + ac1)*2, ap[0] + (size_t)ar1*DD + (KB) + ac1); \
    CPASYNC16(_b + (1*HPART + ar0*HLD + ac0)*2, ap[1] + (size_t)ar0*DD + (KB) + ac0); \
    CPASYNC16(_b + (1*HPART + ar1*HLD + ac1)*2, ap[1] + (size_t)ar1*DD + (KB) + ac1); \
    CPASYNC16(_b + (2*HPART + ar0*HLD + ac0)*2, bp[0] + (size_t)ar0*DD + (KB) + ac0); \
    CPASYNC16(_b + (2*HPART + ar1*HLD + ac1)*2, bp[0] + (size_t)ar1*DD + (KB) + ac1); \
    CPASYNC16(_b + (3*HPART + ar0*HLD + ac0)*2, bp[1] + (size_t)ar0*DD + (KB) + ac0); \
    CPASYNC16(_b + (3*HPART + ar1*HLD + ac1)*2, bp[1] + (size_t)ar1*DD + (KB) + ac1); \
    CPCOMMIT(); \
} while (0)

    PREF(0, 0);
    CPWAIT0();
    __syncthreads();

    for (int kt = 0; kt < 32; ++kt) {
        if (kt + 1 < 32) PREF((kt + 1) & 1, (kt + 1) * 32);
        __half* Asb = smh + (kt & 1) * HBUF;
        __half* Bsb = Asb + 2 * HPART;
#pragma unroll
        for (int ks = 0; ks < 2; ++ks) {
            wmma::fragment<wmma::matrix_a, 16, 16, 16, __half, wmma::row_major> a0f[2], a1f[2];
            wmma::fragment<wmma::matrix_b, 16, 16, 16, __half, wmma::col_major> b0f[4], b1f[4];
#pragma unroll
            for (int mi = 0; mi < 2; ++mi) {
                wmma::load_matrix_sync(a0f[mi], Asb + 0*HPART + (wm*32 + mi*16)*HLD + ks*16, HLD);
                wmma::load_matrix_sync(a1f[mi], Asb + 1*HPART + (wm*32 + mi*16)*HLD + ks*16, HLD);
            }
#pragma unroll
            for (int ni = 0; ni < 4; ++ni) {
                wmma::load_matrix_sync(b0f[ni], Bsb + 0*HPART + (wn*64 + ni*16)*HLD + ks*16, HLD);
                wmma::load_matrix_sync(b1f[ni], Bsb + 1*HPART + (wn*64 + ni*16)*HLD + ks*16, HLD);
            }
#pragma unroll
            for (int mi = 0; mi < 2; ++mi)
#pragma unroll
                for (int ni = 0; ni < 4; ++ni) {
                    wmma::mma_sync(acc[mi][ni], a0f[mi], b0f[ni], acc[mi][ni]);
                    wmma::mma_sync(acc[mi][ni], a0f[mi], b1f[ni], acc[mi][ni]);
                    wmma::mma_sync(acc[mi][ni], a1f[mi], b0f[ni], acc[mi][ni]);
                }
        }
        CPWAIT0();
        __syncthreads();
    }
#undef PREF

    if (mode == 0) {
#pragma unroll
        for (int mi = 0; mi < 2; ++mi)
#pragma unroll
            for (int ni = 0; ni < 4; ++ni) {
                int r = row0 + wm*32 + mi*16;
                int c = col0 + wn*64 + ni*16;
                wmma::store_matrix_sync(C + (size_t)r*DD + c, acc[mi][ni], DD, wmma::mem_row_major);
            }
    } else {
        float* stage = (float*)smh;
#pragma unroll
        for (int mi = 0; mi < 2; ++mi)
#pragma unroll
            for (int ni = 0; ni < 4; ++ni)
                wmma::store_matrix_sync(stage + (wm*32 + mi*16)*132 + wn*64 + ni*16,
                                        acc[mi][ni], 132, wmma::mem_row_major);
        __syncthreads();
#pragma unroll 8
        for (int idx = tid; idx < 128*128; idx += 256) {
            int r = idx >> 7, c = idx & 127;
            float v = stage[r*132 + c];
            int gr = row0 + r;
            int gc = col0 + c;
            int b = gr >> 11, n = gr & (NN - 1);
            int hh = gc >> 6, dh = gc & (DH - 1);
            size_t o = (((size_t)b*HH + hh)*NN + n)*DH + dh;
            __nv_bfloat16 h = __float2bfloat16(v);
            SH[o] = h;
            SM[o] = __float2bfloat16(v - __bfloat162float(h));
        }
    }
}

// ---------------- LayerNorm + head scatter ----------------
__global__ void __launch_bounds__(256) ln_scatter_kernel(
    const float* __restrict__ Y, const float* __restrict__ gam,
    const float* __restrict__ bet, float* __restrict__ O,
    __nv_bfloat16* __restrict__ Oh, __nv_bfloat16* __restrict__ Om)
{
    int row = blockIdx.x, t = threadIdx.x;
    const float* y = Y + (size_t)row * DD;
    float x0 = y[t], x1 = y[t+256], x2 = y[t+512], x3 = y[t+768];
    float s = x0+x1+x2+x3;
    float q = x0*x0 + x1*x1 + x2*x2 + x3*x3;
#pragma unroll
    for (int off = 16; off; off >>= 1) {
        s += __shfl_xor_sync(0xffffffffu, s, off);
        q += __shfl_xor_sync(0xffffffffu, q, off);
    }
    __shared__ float ss[8], sq[8];
    __shared__ float smu, srstd;
    if ((t & 31) == 0) { ss[t>>5] = s; sq[t>>5] = q; }
    __syncthreads();
    if (t == 0) {
        float S = 0.f, Q = 0.f;
#pragma unroll
        for (int i = 0; i < 8; ++i) { S += ss[i]; Q += sq[i]; }
        float mu = S * (1.0f/DD);
        float var = Q * (1.0f/DD) - mu*mu;
        smu = mu; srstd = rsqrtf(var + 1e-5f);
    }
    __syncthreads();
    float mu = smu, rs = srstd;
    int b = row >> 11, n = row & (NN-1);
    float xs[4] = {x0, x1, x2, x3};
#pragma unroll
    for (int i = 0; i < 4; ++i) {
        int d = t + i*256;
        float v = (xs[i] - mu) * rs * gam[d] + bet[d];
        size_t o = (((size_t)b*HH + (d>>6))*NN + n)*DH + (d & (DH-1));
        O[o] = v;
        __nv_bfloat16 h = __float2bfloat16(v);
        Oh[o] = h;
        Om[o] = __float2bfloat16(v - __bfloat162float(h));
    }
}

// ---------------- S0 (fp32 selection path) ----------------
__global__ void __launch_bounds__(256) s0_kernel(
    const float* __restrict__ Qv, const float* __restrict__ Kv, float* __restrict__ S0)
{
    int b  = blockIdx.z;
    int j0 = blockIdx.y << 6, m0 = blockIdx.x << 6;
    int tid = threadIdx.x;
    size_t outbase = ((size_t)b*NN + j0)*MM + m0;
    if (m0 >= j0 + 64) {
        for (int idx = tid; idx < 4096; idx += 256) {
            int jj = idx >> 6, mm = idx & 63;
            S0[outbase + (size_t)jj*MM + mm] = 0.f;
        }
        return;
    }
    __shared__ float Qs[64][68];
    __shared__ float Kts[64][64];
    const float* Qb = Qv + (((size_t)b*HH + 0)*NN + j0)*DH;
    const float* Kb = Kv + (((size_t)b*HH + 0)*NN + m0)*DH;
    int r = tid >> 2, c0 = (tid & 3) << 4;
#pragma unroll
    for (int u = 0; u < 4; ++u) {
        float4 v = *(const float4*)(Qb + (size_t)r*DH + c0 + u*4);
        Qs[r][c0+u*4+0] = v.x; Qs[r][c0+u*4+1] = v.y; Qs[r][c0+u*4+2] = v.z; Qs[r][c0+u*4+3] = v.w;
        float4 w = *(const float4*)(Kb + (size_t)r*DH + c0 + u*4);
        Kts[c0+u*4+0][r] = w.x; Kts[c0+u*4+1][r] = w.y; Kts[c0+u*4+2][r] = w.z; Kts[c0+u*4+3][r] = w.w;
    }
    __syncthreads();
    int tx = tid & 15, ty = tid >> 4;
    float acc[4][4] = {};
#pragma unroll 8
    for (int k = 0; k < 64; ++k) {
        float a0 = Qs[ty*4+0][k], a1 = Qs[ty*4+1][k];
        float a2 = Qs[ty*4+2][k], a3 = Qs[ty*4+3][k];
        float4 b4 = *(const float4*)&Kts[k][tx*4];
        acc[0][0] += a0*b4.x; acc[0][1] += a0*b4.y; acc[0][2] += a0*b4.z; acc[0][3] += a0*b4.w;
        acc[1][0] += a1*b4.x; acc[1][1] += a1*b4.y; acc[1][2] += a1*b4.z; acc[1][3] += a1*b4.w;
        acc[2][0] += a2*b4.x; acc[2][1] += a2*b4.y; acc[2][2] += a2*b4.z; acc[2][3] += a2*b4.w;
        acc[3][0] += a3*b4.x; acc[3][1] += a3*b4.y; acc[3][2] += a3*b4.z; acc[3][3] += a3*b4.w;
    }
#pragma unroll
    for (int i = 0; i < 4; ++i) {
        int j = j0 + ty*4 + i;
        int mb = m0 + tx*4;
        float4 w;
        w.x = ((mb+0) == 0 || (mb+0) >= j) ? 0.f : fmaxf(acc[i][0]*0.125f, 0.f);
        w.y = ((mb+1) == 0 || (mb+1) >= j) ? 0.f : fmaxf(acc[i][1]*0.125f, 0.f);
        w.z = ((mb+2) == 0 || (mb+2) >= j) ? 0.f : fmaxf(acc[i][2]*0.125f, 0.f);
        w.w = ((mb+3) == 0 || (mb+3) >= j) ? 0.f : fmaxf(acc[i][3]*0.125f, 0.f);
        *(float4*)(S0 + ((size_t)b*NN + j)*MM + mb) = w;
    }
}

// ---------------- Finit ----------------
__global__ void __launch_bounds__(256) finit_kernel(
    const float* __restrict__ S0, float* __restrict__ Fi)
{
    int b = blockIdx.y;
    int col = (blockIdx.x << 6) + (threadIdx.x & 63);
    int part = threadIdx.x >> 6;
    const float* base = S0 + ((size_t)b*NN + part*256)*MM + col;
    float s = 0.f;
#pragma unroll 4
    for (int r = 0; r < 256; ++r) s += base[(size_t)r*MM];
    __shared__ float ps[256];
    ps[threadIdx.x] = s;
    __syncthreads();
    if (threadIdx.x < 64) {
        Fi[b*MM + (blockIdx.x << 6) + threadIdx.x] =
            ps[threadIdx.x] + ps[threadIdx.x+64] + ps[threadIdx.x+128] + ps[threadIdx.x+192];
    }
}

// ---------------- scan body: 256 threads, 8 candidates/thread, redux argmax ----------------
// active = alive && pos < i (pos<1024 always < i since i>=1024). Tie-break smallest pos.
__device__ void scan_body(char* smc, int b,
                          const float* __restrict__ S0, const float* __restrict__ Fi,
                          int* __restrict__ evict)
{
    uint32_t* wv = (uint32_t*)smc;            // [2][8]
    int* wp = (int*)(smc + 64);               // [2][8]
    int t = threadIdx.x;
    int lane = t & 31, w = t >> 5;            // 8 warps
    const float* Sb = S0 + (size_t)b*NN*MM;
    float f[8], a[8], bb[8];
    bool alive[8];
#pragma unroll
    for (int k = 0; k < 8; ++k) {
        int pos = t + 256*k;
        f[k] = Fi[b*MM + pos];
        alive[k] = true;
        evict[b*MM + pos] = BIGV;
        a[k] = 0.f;
        bb[k] = Sb[(size_t)1024*MM + pos];
    }
    __syncthreads();

    for (int i = 1024; i < 2048; ++i) {
        int pb = i & 1;
        int ld = (i + 1 < 2048) ? i + 1 : 2047;
        const float* nrow = Sb + (size_t)ld*MM;
        uint32_t v = 0u; int p = 0x7fffffff;
#pragma unroll
        for (int k = 0; k < 8; ++k) {
            f[k] += a[k];
            a[k] = bb[k];
            bb[k] = nrow[t + 256*k];
            int pos = t + 256*k;
            bool act = alive[k] && (pos < i);
            uint32_t vk = __float_as_uint(f[k]);
            if (act && (vk > v || (vk == v && pos < p))) { v = vk; p = pos; }
        }
        uint32_t vmax = __reduce_max_sync(0xffffffffu, v);
        int peq = (v == vmax && p != 0x7fffffff) ? p : 0x7fffffff;
        int pmin = __reduce_min_sync(0xffffffffu, peq);
        if (lane == 0) { wv[pb*8 + w] = vmax; wp[pb*8 + w] = pmin; }
        __syncthreads();
        uint32_t v2 = (lane < 8) ? wv[pb*8 + lane] : 0u;
        int p2 = (lane < 8) ? wp[pb*8 + lane] : 0x7fffffff;
        uint32_t gmax = __reduce_max_sync(0xffffffffu, v2);
        int gq = (v2 == gmax && p2 != 0x7fffffff) ? p2 : 0x7fffffff;
        int gp = __reduce_min_sync(0xffffffffu, gq);
        if ((gp & 255) == t) {
            int k = gp >> 8;
            alive[k] = false;
            evict[b*MM + gp] = i;
        }
        // no trailing sync: next iter writes the other parity buffer
    }
}

// ---------------- attention body (raw mma, register softmax) ----------------
#define AT_LDB 72
#define ATILE (64*AT_LDB)
#define AT3_SMEM (8*ATILE*2 + 2*64*4)

template<bool USE_EV>
__device__ void attn_body(char* smc, int bq, int h, int b,
    const __nv_bfloat16* __restrict__ Qhg, const __nv_bfloat16* __restrict__ Qmg,
    const __nv_bfloat16* __restrict__ Khg, const __nv_bfloat16* __restrict__ Kmg,
    const __nv_bfloat16* __restrict__ Vhg, const __nv_bfloat16* __restrict__ Vmg,
    const int* __restrict__ ev_g,
    __half* __restrict__ Aa, __half* __restrict__ Ab)
{
    uint32_t sb = cvta_s(smc);
    const uint32_t oKh[2] = { 0u,        2u*ATILE*2 };
    const uint32_t oKm[2] = { ATILE*2,   3u*ATILE*2 };
    const uint32_t oVh[2] = { 4u*ATILE*2, 5u*ATILE*2 };
    const uint32_t oVm[2] = { 6u*ATILE*2, 7u*ATILE*2 };
    const uint32_t oEv = 8u*ATILE*2;
    const uint32_t oQh = oVh[0];
    const uint32_t oQm = oVm[0];

    int nq0 = bq << 7;
    int tid = threadIdx.x;
    int lane = tid & 31, wm = tid >> 5;
    size_t head_off = ((size_t)b*HH + h)*NN;

    {
        int qr = tid >> 1, qc = (tid & 1) * 32;
        const __nv_bfloat16* qh = Qhg + (head_off + nq0)*DH;
        const __nv_bfloat16* qm = Qmg + (head_off + nq0)*DH;
#pragma unroll
        for (int u = 0; u < 4; ++u) {
            *(uint4*)(smc + oQh + (qr*AT_LDB + qc + u*8)*2) = *(const uint4*)(qh + (size_t)qr*DH + qc + u*8);
            *(uint4*)(smc + oQm + (qr*AT_LDB + qc + u*8)*2) = *(const uint4*)(qm + (size_t)qr*DH + qc + u*8);
        }
        int klr = tid >> 2, klc = (tid & 3) * 16;
        const __nv_bfloat16* kh = Khg + head_off*DH;
        const __nv_bfloat16* km = Kmg + head_off*DH;
        CPASYNC16(sb + oKh[0] + (klr*AT_LDB + klc)*2,     kh + (size_t)klr*DH + klc);
        CPASYNC16(sb + oKh[0] + (klr*AT_LDB + klc + 8)*2, kh + (size_t)klr*DH + klc + 8);
        CPASYNC16(sb + oKm[0] + (klr*AT_LDB + klc)*2,     km + (size_t)klr*DH + klc);
        CPASYNC16(sb + oKm[0] + (klr*AT_LDB + klc + 8)*2, km + (size_t)klr*DH + klc + 8);
        if (USE_EV && tid < 64) CPASYNC4(sb + oEv + tid*4, ev_g + b*MM + tid);
        CPCOMMIT();
    }
    __syncthreads();

    uint32_t qfh[4][4], qfm[4][4];
    {
        int qrow = wm*16 + (lane & 7) + ((lane & 8) ? 8 : 0);
        int qsel = (lane & 16) ? 8 : 0;
#pragma unroll
        for (int kc = 0; kc < 4; ++kc) {
            uint32_t a = sb + oQh + (qrow*AT_LDB + kc*16 + qsel)*2;
            LDSM_X4(qfh[kc][0], qfh[kc][1], qfh[kc][2], qfh[kc][3], a);
            uint32_t c = sb + oQm + (qrow*AT_LDB + kc*16 + qsel)*2;
            LDSM_X4(qfm[kc][0], qfm[kc][1], qfm[kc][2], qfm[kc][3], c);
        }
    }
    __syncthreads();

    {
        int klr = tid >> 2, klc = (tid & 3) * 16;
        const __nv_bfloat16* vh = Vhg + head_off*DH;
        const __nv_bfloat16* vm = Vmg + head_off*DH;
        CPASYNC16(sb + oVh[0] + (klr*AT_LDB + klc)*2,     vh + (size_t)klr*DH + klc);
        CPASYNC16(sb + oVh[0] + (klr*AT_LDB + klc + 8)*2, vh + (size_t)klr*DH + klc + 8);
        CPASYNC16(sb + oVm[0] + (klr*AT_LDB + klc)*2,     vm + (size_t)klr*DH + klc);
        CPASYNC16(sb + oVm[0] + (klr*AT_LDB + klc + 8)*2, vm + (size_t)klr*DH + klc + 8);
        CPCOMMIT();
    }
    CPWAIT0();
    __syncthreads();

    float oacc[8][4];
#pragma unroll
    for (int ns = 0; ns < 8; ++ns)
#pragma unroll
        for (int e = 0; e < 4; ++e) oacc[ns][e] = 0.f;
    float dr0 = 0.f, dr1 = 0.f;
    int r0g = nq0 + wm*16 + (lane >> 2);
    int r1g = r0g + 8;
    int l15 = lane & 15, lr7 = l15 & 7, lh8 = (l15 >> 3) * 8;
    int ntiles = 2*bq + 2;

    for (int kt = 0; kt < ntiles; ++kt) {
        int p = kt & 1;
        int m0 = kt << 6;
        if (kt + 1 < ntiles) {
            int pn = p ^ 1, m0n = m0 + 64;
            int klr = tid >> 2, klc = (tid & 3) * 16;
            const __nv_bfloat16* kh = Khg + (head_off + m0n)*DH;
            const __nv_bfloat16* km = Kmg + (head_off + m0n)*DH;
            const __nv_bfloat16* vh = Vhg + (head_off + m0n)*DH;
            const __nv_bfloat16* vm = Vmg + (head_off + m0n)*DH;
            CPASYNC16(sb + oKh[pn] + (klr*AT_LDB + klc)*2,     kh + (size_t)klr*DH + klc);
            CPASYNC16(sb + oKh[pn] + (klr*AT_LDB + klc + 8)*2, kh + (size_t)klr*DH + klc + 8);
            CPASYNC16(sb + oKm[pn] + (klr*AT_LDB + klc)*2,     km + (size_t)klr*DH + klc);
            CPASYNC16(sb + oKm[pn] + (klr*AT_LDB + klc + 8)*2, km + (size_t)klr*DH + klc + 8);
            CPASYNC16(sb + oVh[pn] + (klr*AT_LDB + klc)*2,     vh + (size_t)klr*DH + klc);
            CPASYNC16(sb + oVh[pn] + (klr*AT_LDB + klc + 8)*2, vh + (size_t)klr*DH + klc + 8);
            CPASYNC16(sb + oVm[pn] + (klr*AT_LDB + klc)*2,     vm + (size_t)klr*DH + klc);
            CPASYNC16(sb + oVm[pn] + (klr*AT_LDB + klc + 8)*2, vm + (size_t)klr*DH + klc + 8);
            if (USE_EV && tid < 64) CPASYNC4(sb + oEv + pn*256 + tid*4, ev_g + b*MM + m0n + tid);
            CPCOMMIT();
        }

        float sacc[8][4];
#pragma unroll
        for (int ns = 0; ns < 8; ++ns)
#pragma unroll
            for (int e = 0; e < 4; ++e) sacc[ns][e] = 0.f;
#pragma unroll
        for (int kc = 0; kc < 4; ++kc) {
#pragma unroll
            for (int ns = 0; ns < 8; ++ns) {
                uint32_t kb0, kb1, kc0, kc1;
                uint32_t ak = sb + oKh[p] + ((ns*8 + lr7)*AT_LDB + kc*16 + lh8)*2;
                uint32_t am = sb + oKm[p] + ((ns*8 + lr7)*AT_LDB + kc*16 + lh8)*2;
                LDSM_X2(kb0, kb1, ak);
                LDSM_X2(kc0, kc1, am);
                MMA_BF16(sacc[ns], qfh[kc][0], qfh[kc][1], qfh[kc][2], qfh[kc][3], kb0, kb1);
                MMA_BF16(sacc[ns], qfm[kc][0], qfm[kc][1], qfm[kc][2], qfm[kc][3], kb0, kb1);
                MMA_BF16(sacc[ns], qfh[kc][0], qfh[kc][1], qfh[kc][2], qfh[kc][3], kc0, kc1);
            }
        }

        uint32_t pfh[4][4], pfm[4][4];
#pragma unroll
        for (int ns = 0; ns < 8; ++ns) {
            int cb = ns*8 + (lane & 3)*2;
            int mc = m0 + cb;
            int e0 = USE_EV ? *(const int*)(smc + oEv + p*256 + cb*4)     : BIGV;
            int e1 = USE_EV ? *(const int*)(smc + oEv + p*256 + cb*4 + 4) : BIGV;
            float p0 = ((mc     <= r0g) && (r0g < e0)) ? fexp(sacc[ns][0]*0.125f) : 0.f;
            float p1 = ((mc + 1 <= r0g) && (r0g < e1)) ? fexp(sacc[ns][1]*0.125f) : 0.f;
            float p2 = ((mc     <= r1g) && (r1g < e0)) ? fexp(sacc[ns][2]*0.125f) : 0.f;
            float p3 = ((mc + 1 <= r1g) && (r1g < e1)) ? fexp(sacc[ns][3]*0.125f) : 0.f;
            dr0 += p0 + p1; dr1 += p2 + p3;
            __nv_bfloat162 h01 = __floats2bfloat162_rn(p0, p1);
            __nv_bfloat162 h23 = __floats2bfloat162_rn(p2, p3);
            __nv_bfloat162 g01 = __floats2bfloat162_rn(p0 - __bfloat162float(h01.x),
                                                       p1 - __bfloat162float(h01.y));
            __nv_bfloat162 g23 = __floats2bfloat162_rn(p2 - __bfloat162float(h23.x),
                                                       p3 - __bfloat162float(h23.y));
            int kc2 = ns >> 1, hf = (ns & 1) * 2;
            pfh[kc2][hf]     = *(uint32_t*)&h01;
            pfh[kc2][hf + 1] = *(uint32_t*)&h23;
            pfm[kc2][hf]     = *(uint32_t*)&g01;
            pfm[kc2][hf + 1] = *(uint32_t*)&g23;
        }

#pragma unroll
        for (int kc = 0; kc < 4; ++kc) {
#pragma unroll
            for (int ns = 0; ns < 8; ++ns) {
                uint32_t vb0, vb1, vc0, vc1;
                uint32_t av = sb + oVh[p] + ((kc*16 + lr7 + lh8)*AT_LDB + ns*8)*2;
                uint32_t aw = sb + oVm[p] + ((kc*16 + lr7 + lh8)*AT_LDB + ns*8)*2;
                LDSM_X2T(vb0, vb1, av);
                LDSM_X2T(vc0, vc1, aw);
                MMA_BF16(oacc[ns], pfh[kc][0], pfh[kc][1], pfh[kc][2], pfh[kc][3], vb0, vb1);
                MMA_BF16(oacc[ns], pfh[kc][0], pfh[kc][1], pfh[kc][2], pfh[kc][3], vc0, vc1);
                MMA_BF16(oacc[ns], pfm[kc][0], pfm[kc][1], pfm[kc][2], pfm[kc][3], vb0, vb1);
            }
        }
        CPWAIT0();
        __syncthreads();
    }

    dr0 += __shfl_xor_sync(0xffffffffu, dr0, 1);
    dr0 += __shfl_xor_sync(0xffffffffu, dr0, 2);
    dr1 += __shfl_xor_sync(0xffffffffu, dr1, 1);
    dr1 += __shfl_xor_sync(0xffffffffu, dr1, 2);
    float i0 = 1.0f / dr0, i1 = 1.0f / dr1;

#pragma unroll
    for (int ns = 0; ns < 8; ++ns) {
        int colb = h*DH + ns*8 + (lane & 3)*2;
        {
            float w0 = oacc[ns][0]*i0, w1 = oacc[ns][1]*i0;
            size_t o = ((size_t)b*NN + r0g)*DD + colb;
            __half h0 = __float2half_rn(w0), h1 = __float2half_rn(w1);
            *(__half2*)(Aa + o) = __halves2half2(h0, h1);
            *(__half2*)(Ab + o) = __halves2half2(__float2half_rn(w0 - __half2float(h0)),
                                                 __float2half_rn(w1 - __half2float(h1)));
        }
        {
            float w0 = oacc[ns][2]*i1, w1 = oacc[ns][3]*i1;
            size_t o = ((size_t)b*NN + r1g)*DD + colb;
            __half h0 = __float2half_rn(w0), h1 = __float2half_rn(w1);
            *(__half2*)(Aa + o) = __halves2half2(h0, h1);
            *(__half2*)(Ab + o) = __halves2half2(__float2half_rn(w0 - __half2float(h0)),
                                                 __float2half_rn(w1 - __half2float(h1)));
        }
    }
}

// merged kernel: blocks 0-1 = eviction scan; blocks 2.. = attention for rows < 1024 (no ev needed)
__global__ void __launch_bounds__(256) scan_attnlow_kernel(
    const float* __restrict__ S0, const float* __restrict__ Fi, int* __restrict__ evict,
    const __nv_bfloat16* __restrict__ Qhg, const __nv_bfloat16* __restrict__ Qmg,
    const __nv_bfloat16* __restrict__ Khg, const __nv_bfloat16* __restrict__ Kmg,
    const __nv_bfloat16* __restrict__ Vhg, const __nv_bfloat16* __restrict__ Vmg,
    __half* __restrict__ Aa, __half* __restrict__ Ab)
{
    extern __shared__ char smc[];
    if (blockIdx.x < 2) {
        scan_body(smc, blockIdx.x, S0, Fi, evict);
        return;
    }
    int idx = blockIdx.x - 2;
    int b = idx >> 7;
    int rest = idx & 127;
    int h = rest >> 3;
    int bq = 7 - (rest & 7);    // heavy-first within the low half
    attn_body<false>(smc, bq, h, b, Qhg, Qmg, Khg, Kmg, Vhg, Vmg, nullptr, Aa, Ab);
}

__global__ void __launch_bounds__(256) attn_high_kernel(
    const __nv_bfloat16* __restrict__ Qhg, const __nv_bfloat16* __restrict__ Qmg,
    const __nv_bfloat16* __restrict__ Khg, const __nv_bfloat16* __restrict__ Kmg,
    const __nv_bfloat16* __restrict__ Vhg, const __nv_bfloat16* __restrict__ Vmg,
    const int* __restrict__ ev_g,
    __half* __restrict__ Aa, __half* __restrict__ Ab)
{
    extern __shared__ char smc[];
    int idx = blockIdx.x;
    int b = idx >> 7;
    int rest = idx & 127;
    int h = rest >> 3;
    int bq = 15 - (rest & 7);   // heavy-first
    attn_body<true>(smc, bq, h, b, Qhg, Qmg, Khg, Kmg, Vhg, Vmg, ev_g, Aa, Ab);
}

extern "C" void kernel_launch(void* const* d_in, const int* in_sizes, int n_in,
                              void* d_out, int out_size)
{
    (void)in_sizes; (void)n_in; (void)out_size;
    const float* X  = (const float*)d_in[0];
    const float* Wq = (const float*)d_in[1];
    const float* Wk = (const float*)d_in[2];
    const float* Wv = (const float*)d_in[3];
    const float* Wo = (const float*)d_in[4];
    const float* gq = (const float*)d_in[5];
    const float* bq = (const float*)d_in[6];
    const float* gk = (const float*)d_in[7];
    const float* bk = (const float*)d_in[8];
    float* out = (float*)d_out;

    float *Yq, *Yk, *Qp, *Kp, *S0, *Fi; int* ev;
    cudaGetSymbolAddress((void**)&Yq, g_Yq);
    cudaGetSymbolAddress((void**)&Yk, g_Yk);
    cudaGetSymbolAddress((void**)&Qp, g_Q);
    cudaGetSymbolAddress((void**)&Kp, g_K);
    cudaGetSymbolAddress((void**)&S0, g_S0);
    cudaGetSymbolAddress((void**)&Fi, g_Fi);
    cudaGetSymbolAddress((void**)&ev, g_ev);
    __half *hXa,*hXb,*hWqa,*hWqb,*hWka,*hWkb,*hWva,*hWvb,*hWoa,*hWob,*hAa,*hAb;
    cudaGetSymbolAddress((void**)&hXa, g_hXa);   cudaGetSymbolAddress((void**)&hXb, g_hXb);
    cudaGetSymbolAddress((void**)&hWqa, g_hWqa); cudaGetSymbolAddress((void**)&hWqb, g_hWqb);
    cudaGetSymbolAddress((void**)&hWka, g_hWka); cudaGetSymbolAddress((void**)&hWkb, g_hWkb);
    cudaGetSymbolAddress((void**)&hWva, g_hWva); cudaGetSymbolAddress((void**)&hWvb, g_hWvb);
    cudaGetSymbolAddress((void**)&hWoa, g_hWoa); cudaGetSymbolAddress((void**)&hWob, g_hWob);
    cudaGetSymbolAddress((void**)&hAa, g_hAa);   cudaGetSymbolAddress((void**)&hAb, g_hAb);
    __nv_bfloat16 *Qh,*Qm,*Kh,*Km,*Vh,*Vm;
    cudaGetSymbolAddress((void**)&Qh, g_Qh); cudaGetSymbolAddress((void**)&Qm, g_Qm);
    cudaGetSymbolAddress((void**)&Kh, g_Kh); cudaGetSymbolAddress((void**)&Km, g_Km);
    cudaGetSymbolAddress((void**)&Vh, g_Vh); cudaGetSymbolAddress((void**)&Vm, g_Vm);

    cudaFuncSetAttribute(scan_attnlow_kernel, cudaFuncAttributeMaxDynamicSharedMemorySize, AT3_SMEM);
    cudaFuncSetAttribute(attn_high_kernel, cudaFuncAttributeMaxDynamicSharedMemorySize, AT3_SMEM);
    cudaFuncSetAttribute(gemm_h2_kernel, cudaFuncAttributeMaxDynamicSharedMemorySize, GH_SMEM);

    dim3 wgrid4(32, 32, 4);
    dim3 ggrid(DD/128, RR/128);

    conv2h_kernel<<<RR*DD/1024, 256>>>(X, hXa, hXb);
    convW4_kernel<<<wgrid4, dim3(32,8)>>>(Wq, Wk, Wv, Wo,
                                          hWqa, hWqb, hWka, hWkb,
                                          hWva, hWvb, hWoa, hWob);
    gemm_h2_kernel<<<ggrid, 256, GH_SMEM>>>(hXa, hXb, hWqa, hWqb, Yq, nullptr, nullptr, 0);
    gemm_h2_kernel<<<ggrid, 256, GH_SMEM>>>(hXa, hXb, hWka, hWkb, Yk, nullptr, nullptr, 0);
    gemm_h2_kernel<<<ggrid, 256, GH_SMEM>>>(hXa, hXb, hWva, hWvb, nullptr, Vh, Vm, 1);
    ln_scatter_kernel<<<RR, 256>>>(Yq, gq, bq, Qp, Qh, Qm);
    ln_scatter_kernel<<<RR, 256>>>(Yk, gk, bk, Kp, Kh, Km);
    s0_kernel<<<dim3(MM/64, NN/64, BB), 256>>>(Qp, Kp, S0);
    finit_kernel<<<dim3(MM/64, BB), 256>>>(S0, Fi);
    scan_attnlow_kernel<<<2 + 256, 256, AT3_SMEM>>>(S0, Fi, ev,
                                                    Qh, Qm, Kh, Km, Vh, Vm, hAa, hAb);
    attn_high_kernel<<<256, 256, AT3_SMEM>>>(Qh, Qm, Kh, Km, Vh, Vm, ev, hAa, hAb);
    gemm_h2_kernel<<<ggrid, 256, GH_SMEM>>>(hAa, hAb, hWoa, hWob, out, nullptr, nullptr, 0);
}

// round 16
// speedup vs baseline: 1.2782x; 1.2782x over previous
#include <cuda_runtime.h>
#include <cuda_bf16.h>
#include <cuda_fp16.h>
#include <mma.h>
#include <cstdint>
#include <cstddef>

using namespace nvcuda;

#define BB 2
#define NN 2048
#define DD 1024
#define HH 16
#define DH 64
#define RR (BB*NN)
#define MM 2048
#define BIGV (1<<30)

// ---------------- scratch ----------------
__device__ float g_Yq[(size_t)RR*DD];
__device__ float g_Yk[(size_t)RR*DD];
__device__ float g_Q[(size_t)BB*HH*NN*DH];
__device__ float g_K[(size_t)BB*HH*NN*DH];
__device__ float g_S0[(size_t)BB*NN*MM];
__device__ float g_Fi[BB*MM];
__device__ int   g_ev[BB*MM];
__device__ __half g_hXa[(size_t)RR*DD], g_hXb[(size_t)RR*DD];
__device__ __half g_hWqa[(size_t)DD*DD], g_hWqb[(size_t)DD*DD];
__device__ __half g_hWka[(size_t)DD*DD], g_hWkb[(size_t)DD*DD];
__device__ __half g_hWva[(size_t)DD*DD], g_hWvb[(size_t)DD*DD];
__device__ __half g_hWoa[(size_t)DD*DD], g_hWob[(size_t)DD*DD];
__device__ __half g_hAa[(size_t)RR*DD], g_hAb[(size_t)RR*DD];
__device__ __nv_bfloat16 g_Qh[(size_t)BB*HH*NN*DH], g_Qm[(size_t)BB*HH*NN*DH];
__device__ __nv_bfloat16 g_Kh[(size_t)BB*HH*NN*DH], g_Km[(size_t)BB*HH*NN*DH];
__device__ __nv_bfloat16 g_Vh[(size_t)BB*HH*NN*DH], g_Vm[(size_t)BB*HH*NN*DH];

// fast exp on FMA pipe (no MUFU)
__device__ __forceinline__ float fexp(float x) {
    float t = x * 1.4426950408889634f;
    int ei = __float2int_rn(t);
    float f = t - (float)ei;
    float p = 1.3333558146428443e-3f;
    p = fmaf(p, f, 9.6181291076284772e-3f);
    p = fmaf(p, f, 5.5504108664821580e-2f);
    p = fmaf(p, f, 2.4022650695910072e-1f);
    p = fmaf(p, f, 6.9314718055994531e-1f);
    p = fmaf(p, f, 1.0f);
    return __int_as_float(__float_as_int(p) + (ei << 23));
}

__device__ __forceinline__ uint32_t cvta_s(const void* p) {
    uint32_t a;
    asm("{ .reg .u64 t; cvta.to.shared.u64 t, %1; cvt.u32.u64 %0, t; }" : "=r"(a) : "l"(p));
    return a;
}
#define LDSM_X4(r0,r1,r2,r3,a) \
    asm volatile("ldmatrix.sync.aligned.m8n8.x4.shared.b16 {%0,%1,%2,%3}, [%4];" \
        : "=r"(r0),"=r"(r1),"=r"(r2),"=r"(r3) : "r"(a))
#define LDSM_X2(r0,r1,a) \
    asm volatile("ldmatrix.sync.aligned.m8n8.x2.shared.b16 {%0,%1}, [%2];" \
        : "=r"(r0),"=r"(r1) : "r"(a))
#define LDSM_X2T(r0,r1,a) \
    asm volatile("ldmatrix.sync.aligned.m8n8.x2.trans.shared.b16 {%0,%1}, [%2];" \
        : "=r"(r0),"=r"(r1) : "r"(a))
#define MMA_BF16(d,a0,a1,a2,a3,b0,b1) \
    asm volatile("mma.sync.aligned.m16n8k16.row.col.f32.bf16.bf16.f32 " \
        "{%0,%1,%2,%3}, {%4,%5,%6,%7}, {%8,%9}, {%0,%1,%2,%3};" \
        : "+f"((d)[0]),"+f"((d)[1]),"+f"((d)[2]),"+f"((d)[3]) \
        : "r"(a0),"r"(a1),"r"(a2),"r"(a3),"r"(b0),"r"(b1))
#define CPASYNC16(s,g) asm volatile("cp.async.ca.shared.global [%0], [%1], 16;" :: "r"(s), "l"(g))
#define CPASYNC4(s,g)  asm volatile("cp.async.ca.shared.global [%0], [%1], 4;"  :: "r"(s), "l"(g))
#define CPCOMMIT() asm volatile("cp.async.commit_group;" ::: "memory")
#define CPWAIT0()  asm volatile("cp.async.wait_group 0;" ::: "memory")

// ---------------- conversions ----------------
__global__ void __launch_bounds__(256) conv2h_kernel(
    const float* __restrict__ X, __half* __restrict__ H, __half* __restrict__ M)
{
    int i = (blockIdx.x * 256 + threadIdx.x) * 4;
    float4 v = *(const float4*)(X + i);
    __half h0 = __float2half_rn(v.x), h1 = __float2half_rn(v.y);
    __half h2 = __float2half_rn(v.z), h3 = __float2half_rn(v.w);
    __half2 ha = __halves2half2(h0, h1), hb = __halves2half2(h2, h3);
    __half2 ma = __halves2half2(__float2half_rn(v.x - __half2float(h0)),
                                __float2half_rn(v.y - __half2float(h1)));
    __half2 mb = __halves2half2(__float2half_rn(v.z - __half2float(h2)),
                                __float2half_rn(v.w - __half2float(h3)));
    *(__half2*)(H + i) = ha; *(__half2*)(H + i + 2) = hb;
    *(__half2*)(M + i) = ma; *(__half2*)(M + i + 2) = mb;
}

// 4 weight transposes fused: blockIdx.z selects the matrix
__global__ void __launch_bounds__(256) convW4_kernel(
    const float* __restrict__ W0, const float* __restrict__ W1,
    const float* __restrict__ W2, const float* __restrict__ W3,
    __half* __restrict__ TH0, __half* __restrict__ TM0,
    __half* __restrict__ TH1, __half* __restrict__ TM1,
    __half* __restrict__ TH2, __half* __restrict__ TM2,
    __half* __restrict__ TH3, __half* __restrict__ TM3)
{
    const float* W = (blockIdx.z == 0) ? W0 : (blockIdx.z == 1) ? W1 : (blockIdx.z == 2) ? W2 : W3;
    __half* TH = (blockIdx.z == 0) ? TH0 : (blockIdx.z == 1) ? TH1 : (blockIdx.z == 2) ? TH2 : TH3;
    __half* TM = (blockIdx.z == 0) ? TM0 : (blockIdx.z == 1) ? TM1 : (blockIdx.z == 2) ? TM2 : TM3;
    __shared__ float tile[32][33];
    int n0 = blockIdx.x * 32, k0 = blockIdx.y * 32;
    int tx = threadIdx.x, ty = threadIdx.y;
#pragma unroll
    for (int i = 0; i < 32; i += 8)
        tile[ty + i][tx] = W[(size_t)(k0 + ty + i) * DD + n0 + tx];
    __syncthreads();
#pragma unroll
    for (int i = 0; i < 32; i += 8) {
        float v = tile[tx][ty + i];
        __half h = __float2half_rn(v);
        size_t o = (size_t)(n0 + ty + i) * DD + k0 + tx;
        TH[o] = h;
        TM[o] = __float2half_rn(v - __half2float(h));
    }
}

// ---------------- fp16 2-split WMMA GEMM, 128x128 tile, cp.async, 1 sync/iter ----------------
#define HLD 40
#define HPART (128*HLD)
#define HBUF (4*HPART)
#define GH_SMEM (2*HBUF*2)

__global__ void __launch_bounds__(256) gemm_h2_kernel(
    const __half* __restrict__ A0, const __half* __restrict__ A1,
    const __half* __restrict__ B0, const __half* __restrict__ B1,
    float* __restrict__ C,
    __nv_bfloat16* __restrict__ SH, __nv_bfloat16* __restrict__ SM,
    int mode)
{
    extern __shared__ __half smh[];
    uint32_t sb = cvta_s(smh);
    int tid = threadIdx.x, wid = tid >> 5;
    int wm = wid & 3, wn = wid >> 2;
    int row0 = blockIdx.y * 128, col0 = blockIdx.x * 128;

    const __half* ap[2] = { A0 + (size_t)row0 * DD, A1 + (size_t)row0 * DD };
    const __half* bp[2] = { B0 + (size_t)col0 * DD, B1 + (size_t)col0 * DD };

    int ar0 = (tid * 2) >> 2,     ac0 = ((tid * 2) & 3) * 8;
    int ar1 = (tid * 2 + 1) >> 2, ac1 = ((tid * 2 + 1) & 3) * 8;

    wmma::fragment<wmma::accumulator, 16, 16, 16, float> acc[2][4];
#pragma unroll
    for (int i = 0; i < 2; ++i)
#pragma unroll
        for (int j = 0; j < 4; ++j) wmma::fill_fragment(acc[i][j], 0.0f);

#define PREF(BUF, KB) do { \
    uint32_t _b = sb + (BUF)*HBUF*2; \
    CPASYNC16(_b + (0*HPART + ar0*HLD + ac0)*2, ap[0] + (size_t)ar0*DD + (KB) + ac0); \
    CPASYNC16(_b + (0*HPART + ar1*HLD + ac1)*2, ap[0] + (size_t)ar1*DD + (KB) + ac1); \
    CPASYNC16(_b + (1*HPART + ar0*HLD + ac0)*2, ap[1] + (size_t)ar0*DD + (KB) + ac0); \
    CPASYNC16(_b + (1*HPART + ar1*HLD + ac1)*2, ap[1] + (size_t)ar1*DD + (KB) + ac1); \
    CPASYNC16(_b + (2*HPART + ar0*HLD + ac0)*2, bp[0] + (size_t)ar0*DD + (KB) + ac0); \
    CPASYNC16(_b + (2*HPART + ar1*HLD + ac1)*2, bp[0] + (size_t)ar1*DD + (KB) + ac1); \
    CPASYNC16(_b + (3*HPART + ar0*HLD + ac0)*2, bp[1] + (size_t)ar0*DD + (KB) + ac0); \
    CPASYNC16(_b + (3*HPART + ar1*HLD + ac1)*2, bp[1] + (size_t)ar1*DD + (KB) + ac1); \
    CPCOMMIT(); \
} while (0)

    PREF(0, 0);
    CPWAIT0();
    __syncthreads();

    for (int kt = 0; kt < 32; ++kt) {
        if (kt + 1 < 32) PREF((kt + 1) & 1, (kt + 1) * 32);
        __half* Asb = smh + (kt & 1) * HBUF;
        __half* Bsb = Asb + 2 * HPART;
#pragma unroll
        for (int ks = 0; ks < 2; ++ks) {
            wmma::fragment<wmma::matrix_a, 16, 16, 16, __half, wmma::row_major> a0f[2], a1f[2];
            wmma::fragment<wmma::matrix_b, 16, 16, 16, __half, wmma::col_major> b0f[4], b1f[4];
#pragma unroll
            for (int mi = 0; mi < 2; ++mi) {
                wmma::load_matrix_sync(a0f[mi], Asb + 0*HPART + (wm*32 + mi*16)*HLD + ks*16, HLD);
                wmma::load_matrix_sync(a1f[mi], Asb + 1*HPART + (wm*32 + mi*16)*HLD + ks*16, HLD);
            }
#pragma unroll
            for (int ni = 0; ni < 4; ++ni) {
                wmma::load_matrix_sync(b0f[ni], Bsb + 0*HPART + (wn*64 + ni*16)*HLD + ks*16, HLD);
                wmma::load_matrix_sync(b1f[ni], Bsb + 1*HPART + (wn*64 + ni*16)*HLD + ks*16, HLD);
            }
#pragma unroll
            for (int mi = 0; mi < 2; ++mi)
#pragma unroll
                for (int ni = 0; ni < 4; ++ni) {
                    wmma::mma_sync(acc[mi][ni], a0f[mi], b0f[ni], acc[mi][ni]);
                    wmma::mma_sync(acc[mi][ni], a0f[mi], b1f[ni], acc[mi][ni]);
                    wmma::mma_sync(acc[mi][ni], a1f[mi], b0f[ni], acc[mi][ni]);
                }
        }
        CPWAIT0();
        __syncthreads();
    }
#undef PREF

    if (mode == 0) {
#pragma unroll
        for (int mi = 0; mi < 2; ++mi)
#pragma unroll
            for (int ni = 0; ni < 4; ++ni) {
                int r = row0 + wm*32 + mi*16;
                int c = col0 + wn*64 + ni*16;
                wmma::store_matrix_sync(C + (size_t)r*DD + c, acc[mi][ni], DD, wmma::mem_row_major);
            }
    } else {
        float* stage = (float*)smh;
#pragma unroll
        for (int mi = 0; mi < 2; ++mi)
#pragma unroll
            for (int ni = 0; ni < 4; ++ni)
                wmma::store_matrix_sync(stage + (wm*32 + mi*16)*132 + wn*64 + ni*16,
                                        acc[mi][ni], 132, wmma::mem_row_major);
        __syncthreads();
#pragma unroll 8
        for (int idx = tid; idx < 128*128; idx += 256) {
            int r = idx >> 7, c = idx & 127;
            float v = stage[r*132 + c];
            int gr = row0 + r;
            int gc = col0 + c;
            int b = gr >> 11, n = gr & (NN - 1);
            int hh = gc >> 6, dh = gc & (DH - 1);
            size_t o = (((size_t)b*HH + hh)*NN + n)*DH + dh;
            __nv_bfloat16 h = __float2bfloat16(v);
            SH[o] = h;
            SM[o] = __float2bfloat16(v - __bfloat162float(h));
        }
    }
}

// ---------------- LayerNorm + head scatter ----------------
__global__ void __launch_bounds__(256) ln_scatter_kernel(
    const float* __restrict__ Y, const float* __restrict__ gam,
    const float* __restrict__ bet, float* __restrict__ O,
    __nv_bfloat16* __restrict__ Oh, __nv_bfloat16* __restrict__ Om)
{
    int row = blockIdx.x, t = threadIdx.x;
    const float* y = Y + (size_t)row * DD;
    float x0 = y[t], x1 = y[t+256], x2 = y[t+512], x3 = y[t+768];
    float s = x0+x1+x2+x3;
    float q = x0*x0 + x1*x1 + x2*x2 + x3*x3;
#pragma unroll
    for (int off = 16; off; off >>= 1) {
        s += __shfl_xor_sync(0xffffffffu, s, off);
        q += __shfl_xor_sync(0xffffffffu, q, off);
    }
    __shared__ float ss[8], sq[8];
    __shared__ float smu, srstd;
    if ((t & 31) == 0) { ss[t>>5] = s; sq[t>>5] = q; }
    __syncthreads();
    if (t == 0) {
        float S = 0.f, Q = 0.f;
#pragma unroll
        for (int i = 0; i < 8; ++i) { S += ss[i]; Q += sq[i]; }
        float mu = S * (1.0f/DD);
        float var = Q * (1.0f/DD) - mu*mu;
        smu = mu; srstd = rsqrtf(var + 1e-5f);
    }
    __syncthreads();
    float mu = smu, rs = srstd;
    int b = row >> 11, n = row & (NN-1);
    float xs[4] = {x0, x1, x2, x3};
#pragma unroll
    for (int i = 0; i < 4; ++i) {
        int d = t + i*256;
        float v = (xs[i] - mu) * rs * gam[d] + bet[d];
        size_t o = (((size_t)b*HH + (d>>6))*NN + n)*DH + (d & (DH-1));
        O[o] = v;
        __nv_bfloat16 h = __float2bfloat16(v);
        Oh[o] = h;
        Om[o] = __float2bfloat16(v - __bfloat162float(h));
    }
}

// ---------------- S0 (fp32 selection path) ----------------
__global__ void __launch_bounds__(256) s0_kernel(
    const float* __restrict__ Qv, const float* __restrict__ Kv, float* __restrict__ S0)
{
    int b  = blockIdx.z;
    int j0 = blockIdx.y << 6, m0 = blockIdx.x << 6;
    int tid = threadIdx.x;
    size_t outbase = ((size_t)b*NN + j0)*MM + m0;
    if (m0 >= j0 + 64) {
        for (int idx = tid; idx < 4096; idx += 256) {
            int jj = idx >> 6, mm = idx & 63;
            S0[outbase + (size_t)jj*MM + mm] = 0.f;
        }
        return;
    }
    __shared__ float Qs[64][68];
    __shared__ float Kts[64][64];
    const float* Qb = Qv + (((size_t)b*HH + 0)*NN + j0)*DH;
    const float* Kb = Kv + (((size_t)b*HH + 0)*NN + m0)*DH;
    int r = tid >> 2, c0 = (tid & 3) << 4;
#pragma unroll
    for (int u = 0; u < 4; ++u) {
        float4 v = *(const float4*)(Qb + (size_t)r*DH + c0 + u*4);
        Qs[r][c0+u*4+0] = v.x; Qs[r][c0+u*4+1] = v.y; Qs[r][c0+u*4+2] = v.z; Qs[r][c0+u*4+3] = v.w;
        float4 w = *(const float4*)(Kb + (size_t)r*DH + c0 + u*4);
        Kts[c0+u*4+0][r] = w.x; Kts[c0+u*4+1][r] = w.y; Kts[c0+u*4+2][r] = w.z; Kts[c0+u*4+3][r] = w.w;
    }
    __syncthreads();
    int tx = tid & 15, ty = tid >> 4;
    float acc[4][4] = {};
#pragma unroll 8
    for (int k = 0; k < 64; ++k) {
        float a0 = Qs[ty*4+0][k], a1 = Qs[ty*4+1][k];
        float a2 = Qs[ty*4+2][k], a3 = Qs[ty*4+3][k];
        float4 b4 = *(const float4*)&Kts[k][tx*4];
        acc[0][0] += a0*b4.x; acc[0][1] += a0*b4.y; acc[0][2] += a0*b4.z; acc[0][3] += a0*b4.w;
        acc[1][0] += a1*b4.x; acc[1][1] += a1*b4.y; acc[1][2] += a1*b4.z; acc[1][3] += a1*b4.w;
        acc[2][0] += a2*b4.x; acc[2][1] += a2*b4.y; acc[2][2] += a2*b4.z; acc[2][3] += a2*b4.w;
        acc[3][0] += a3*b4.x; acc[3][1] += a3*b4.y; acc[3][2] += a3*b4.z; acc[3][3] += a3*b4.w;
    }
#pragma unroll
    for (int i = 0; i < 4; ++i) {
        int j = j0 + ty*4 + i;
        int mb = m0 + tx*4;
        float4 w;
        w.x = ((mb+0) == 0 || (mb+0) >= j) ? 0.f : fmaxf(acc[i][0]*0.125f, 0.f);
        w.y = ((mb+1) == 0 || (mb+1) >= j) ? 0.f : fmaxf(acc[i][1]*0.125f, 0.f);
        w.z = ((mb+2) == 0 || (mb+2) >= j) ? 0.f : fmaxf(acc[i][2]*0.125f, 0.f);
        w.w = ((mb+3) == 0 || (mb+3) >= j) ? 0.f : fmaxf(acc[i][3]*0.125f, 0.f);
        *(float4*)(S0 + ((size_t)b*NN + j)*MM + mb) = w;
    }
}

// ---------------- Finit ----------------
__global__ void __launch_bounds__(256) finit_kernel(
    const float* __restrict__ S0, float* __restrict__ Fi)
{
    int b = blockIdx.y;
    int col = (blockIdx.x << 6) + (threadIdx.x & 63);
    int part = threadIdx.x >> 6;
    const float* base = S0 + ((size_t)b*NN + part*256)*MM + col;
    float s = 0.f;
#pragma unroll 4
    for (int r = 0; r < 256; ++r) s += base[(size_t)r*MM];
    __shared__ float ps[256];
    ps[threadIdx.x] = s;
    __syncthreads();
    if (threadIdx.x < 64) {
        Fi[b*MM + (blockIdx.x << 6) + threadIdx.x] =
            ps[threadIdx.x] + ps[threadIdx.x+64] + ps[threadIdx.x+128] + ps[threadIdx.x+192];
    }
}

// ---------------- serial eviction scan (1024 threads, redux.sync argmax) ----------------
__global__ void __launch_bounds__(1024) scan_kernel(
    const float* __restrict__ S0, const float* __restrict__ Fi, int* __restrict__ evict)
{
    __shared__ uint32_t wv[2][32];
    __shared__ int wp[2][32];
    int b = blockIdx.x, t = threadIdx.x;
    int lane = t & 31, w = t >> 5;
    float f0 = Fi[b*MM + t];
    float f1 = Fi[b*MM + 1024 + t];
    bool alive0 = true, alive1 = true;
    evict[b*MM + t] = BIGV;
    evict[b*MM + 1024 + t] = BIGV;
    const float* Sb = S0 + (size_t)b*NN*MM;
    float a0 = 0.f, a1 = 0.f;
    float b0 = Sb[(size_t)1024*MM + t], b1 = Sb[(size_t)1024*MM + 1024 + t];
    __syncthreads();

    for (int i = 1024; i < 2048; ++i) {
        int pb = i & 1;
        f0 += a0; f1 += a1;
        a0 = b0; a1 = b1;
        int ld = (i + 1 < 2048) ? i + 1 : 2047;
        const float* nrow = Sb + (size_t)ld*MM;
        b0 = nrow[t]; b1 = nrow[t + 1024];

        bool al1 = alive1 && (t < i - 1024);
        uint32_t v0 = alive0 ? __float_as_uint(f0) : 0u;
        uint32_t v1 = al1 ? __float_as_uint(f1) : 0u;
        bool w1 = (v1 > v0);
        uint32_t v = w1 ? v1 : v0;
        int p = w1 ? 1024 + t : t;
        bool wal = w1 ? al1 : alive0;
        uint32_t vmax = __reduce_max_sync(0xffffffffu, v);
        int peq = (wal && v == vmax) ? p : 0x7fffffff;
        int pmin = __reduce_min_sync(0xffffffffu, peq);
        if (lane == 0) { wv[pb][w] = vmax; wp[pb][w] = pmin; }
        __syncthreads();
        uint32_t v2 = wv[pb][lane]; int p2 = wp[pb][lane];
        uint32_t gmax = __reduce_max_sync(0xffffffffu, v2);
        int gq = (v2 == gmax) ? p2 : 0x7fffffff;
        int gp = __reduce_min_sync(0xffffffffu, gq);
        if (gp == t)             { alive0 = false; evict[b*MM + t] = i; }
        else if (gp == 1024 + t) { alive1 = false; evict[b*MM + 1024 + t] = i; }
    }
}

// ---------------- raw-mma flash attention ----------------
#define AT_LDB 72
#define ATILE (64*AT_LDB)
#define AT3_SMEM (8*ATILE*2 + 2*64*4)

__global__ void __launch_bounds__(256) attn_mma_kernel(
    const __nv_bfloat16* __restrict__ Qhg, const __nv_bfloat16* __restrict__ Qmg,
    const __nv_bfloat16* __restrict__ Khg, const __nv_bfloat16* __restrict__ Kmg,
    const __nv_bfloat16* __restrict__ Vhg, const __nv_bfloat16* __restrict__ Vmg,
    const int* __restrict__ ev_g,
    __half* __restrict__ Aa, __half* __restrict__ Ab)
{
    extern __shared__ char smc[];
    uint32_t sb = cvta_s(smc);
    const uint32_t oKh[2] = { 0u,        2u*ATILE*2 };
    const uint32_t oKm[2] = { ATILE*2,   3u*ATILE*2 };
    const uint32_t oVh[2] = { 4u*ATILE*2, 5u*ATILE*2 };
    const uint32_t oVm[2] = { 6u*ATILE*2, 7u*ATILE*2 };
    const uint32_t oEv = 8u*ATILE*2;
    const uint32_t oQh = oVh[0];
    const uint32_t oQm = oVm[0];

    int bq = (int)gridDim.x - 1 - (int)blockIdx.x;
    int h = blockIdx.y, b = blockIdx.z;
    int nq0 = bq << 7;
    int tid = threadIdx.x;
    int lane = tid & 31, wm = tid >> 5;
    size_t head_off = ((size_t)b*HH + h)*NN;

    {
        int qr = tid >> 1, qc = (tid & 1) * 32;
        const __nv_bfloat16* qh = Qhg + (head_off + nq0)*DH;
        const __nv_bfloat16* qm = Qmg + (head_off + nq0)*DH;
#pragma unroll
        for (int u = 0; u < 4; ++u) {
            *(uint4*)(smc + oQh + (qr*AT_LDB + qc + u*8)*2) = *(const uint4*)(qh + (size_t)qr*DH + qc + u*8);
            *(uint4*)(smc + oQm + (qr*AT_LDB + qc + u*8)*2) = *(const uint4*)(qm + (size_t)qr*DH + qc + u*8);
        }
        int klr = tid >> 2, klc = (tid & 3) * 16;
        const __nv_bfloat16* kh = Khg + head_off*DH;
        const __nv_bfloat16* km = Kmg + head_off*DH;
        CPASYNC16(sb + oKh[0] + (klr*AT_LDB + klc)*2,     kh + (size_t)klr*DH + klc);
        CPASYNC16(sb + oKh[0] + (klr*AT_LDB + klc + 8)*2, kh + (size_t)klr*DH + klc + 8);
        CPASYNC16(sb + oKm[0] + (klr*AT_LDB + klc)*2,     km + (size_t)klr*DH + klc);
        CPASYNC16(sb + oKm[0] + (klr*AT_LDB + klc + 8)*2, km + (size_t)klr*DH + klc + 8);
        if (tid < 64) CPASYNC4(sb + oEv + tid*4, ev_g + b*MM + tid);
        CPCOMMIT();
    }
    __syncthreads();

    uint32_t qfh[4][4], qfm[4][4];
    {
        int qrow = wm*16 + (lane & 7) + ((lane & 8) ? 8 : 0);
        int qsel = (lane & 16) ? 8 : 0;
#pragma unroll
        for (int kc = 0; kc < 4; ++kc) {
            uint32_t a = sb + oQh + (qrow*AT_LDB + kc*16 + qsel)*2;
            LDSM_X4(qfh[kc][0], qfh[kc][1], qfh[kc][2], qfh[kc][3], a);
            uint32_t c = sb + oQm + (qrow*AT_LDB + kc*16 + qsel)*2;
            LDSM_X4(qfm[kc][0], qfm[kc][1], qfm[kc][2], qfm[kc][3], c);
        }
    }
    __syncthreads();

    {
        int klr = tid >> 2, klc = (tid & 3) * 16;
        const __nv_bfloat16* vh = Vhg + head_off*DH;
        const __nv_bfloat16* vm = Vmg + head_off*DH;
        CPASYNC16(sb + oVh[0] + (klr*AT_LDB + klc)*2,     vh + (size_t)klr*DH + klc);
        CPASYNC16(sb + oVh[0] + (klr*AT_LDB + klc + 8)*2, vh + (size_t)klr*DH + klc + 8);
        CPASYNC16(sb + oVm[0] + (klr*AT_LDB + klc)*2,     vm + (size_t)klr*DH + klc);
        CPASYNC16(sb + oVm[0] + (klr*AT_LDB + klc + 8)*2, vm + (size_t)klr*DH + klc + 8);
        CPCOMMIT();
    }
    CPWAIT0();
    __syncthreads();

    float oacc[8][4];
#pragma unroll
    for (int ns = 0; ns < 8; ++ns)
#pragma unroll
        for (int e = 0; e < 4; ++e) oacc[ns][e] = 0.f;
    float dr0 = 0.f, dr1 = 0.f;
    int r0g = nq0 + wm*16 + (lane >> 2);
    int r1g = r0g + 8;
    int l15 = lane & 15, lr7 = l15 & 7, lh8 = (l15 >> 3) * 8;
    int ntiles = 2*bq + 2;

    for (int kt = 0; kt < ntiles; ++kt) {
        int p = kt & 1;
        int m0 = kt << 6;
        if (kt + 1 < ntiles) {
            int pn = p ^ 1, m0n = m0 + 64;
            int klr = tid >> 2, klc = (tid & 3) * 16;
            const __nv_bfloat16* kh = Khg + (head_off + m0n)*DH;
            const __nv_bfloat16* km = Kmg + (head_off + m0n)*DH;
            const __nv_bfloat16* vh = Vhg + (head_off + m0n)*DH;
            const __nv_bfloat16* vm = Vmg + (head_off + m0n)*DH;
            CPASYNC16(sb + oKh[pn] + (klr*AT_LDB + klc)*2,     kh + (size_t)klr*DH + klc);
            CPASYNC16(sb + oKh[pn] + (klr*AT_LDB + klc + 8)*2, kh + (size_t)klr*DH + klc + 8);
            CPASYNC16(sb + oKm[pn] + (klr*AT_LDB + klc)*2,     km + (size_t)klr*DH + klc);
            CPASYNC16(sb + oKm[pn] + (klr*AT_LDB + klc + 8)*2, km + (size_t)klr*DH + klc + 8);
            CPASYNC16(sb + oVh[pn] + (klr*AT_LDB + klc)*2,     vh + (size_t)klr*DH + klc);
            CPASYNC16(sb + oVh[pn] + (klr*AT_LDB + klc + 8)*2, vh + (size_t)klr*DH + klc + 8);
            CPASYNC16(sb + oVm[pn] + (klr*AT_LDB + klc)*2,     vm + (size_t)klr*DH + klc);
            CPASYNC16(sb + oVm[pn] + (klr*AT_LDB + klc + 8)*2, vm + (size_t)klr*DH + klc + 8);
            if (tid < 64) CPASYNC4(sb + oEv + pn*256 + tid*4, ev_g + b*MM + m0n + tid);
            CPCOMMIT();
        }

        float sacc[8][4];
#pragma unroll
        for (int ns = 0; ns < 8; ++ns)
#pragma unroll
            for (int e = 0; e < 4; ++e) sacc[ns][e] = 0.f;
#pragma unroll
        for (int kc = 0; kc < 4; ++kc) {
#pragma unroll
            for (int ns = 0; ns < 8; ++ns) {
                uint32_t kb0, kb1, kc0, kc1;
                uint32_t ak = sb + oKh[p] + ((ns*8 + lr7)*AT_LDB + kc*16 + lh8)*2;
                uint32_t am = sb + oKm[p] + ((ns*8 + lr7)*AT_LDB + kc*16 + lh8)*2;
                LDSM_X2(kb0, kb1, ak);
                LDSM_X2(kc0, kc1, am);
                MMA_BF16(sacc[ns], qfh[kc][0], qfh[kc][1], qfh[kc][2], qfh[kc][3], kb0, kb1);
                MMA_BF16(sacc[ns], qfm[kc][0], qfm[kc][1], qfm[kc][2], qfm[kc][3], kb0, kb1);
                MMA_BF16(sacc[ns], qfh[kc][0], qfh[kc][1], qfh[kc][2], qfh[kc][3], kc0, kc1);
            }
        }

        uint32_t pfh[4][4], pfm[4][4];
#pragma unroll
        for (int ns = 0; ns < 8; ++ns) {
            int cb = ns*8 + (lane & 3)*2;
            int mc = m0 + cb;
            int e0 = *(const int*)(smc + oEv + p*256 + cb*4);
            int e1 = *(const int*)(smc + oEv + p*256 + cb*4 + 4);
            float p0 = ((mc     <= r0g) && (r0g < e0)) ? fexp(sacc[ns][0]*0.125f) : 0.f;
            float p1 = ((mc + 1 <= r0g) && (r0g < e1)) ? fexp(sacc[ns][1]*0.125f) : 0.f;
            float p2 = ((mc     <= r1g) && (r1g < e0)) ? fexp(sacc[ns][2]*0.125f) : 0.f;
            float p3 = ((mc + 1 <= r1g) && (r1g < e1)) ? fexp(sacc[ns][3]*0.125f) : 0.f;
            dr0 += p0 + p1; dr1 += p2 + p3;
            __nv_bfloat162 h01 = __floats2bfloat162_rn(p0, p1);
            __nv_bfloat162 h23 = __floats2bfloat162_rn(p2, p3);
            __nv_bfloat162 g01 = __floats2bfloat162_rn(p0 - __bfloat162float(h01.x),
                                                       p1 - __bfloat162float(h01.y));
            __nv_bfloat162 g23 = __floats2bfloat162_rn(p2 - __bfloat162float(h23.x),
                                                       p3 - __bfloat162float(h23.y));
            int kc2 = ns >> 1, hf = (ns & 1) * 2;
            pfh[kc2][hf]     = *(uint32_t*)&h01;
            pfh[kc2][hf + 1] = *(uint32_t*)&h23;
            pfm[kc2][hf]     = *(uint32_t*)&g01;
            pfm[kc2][hf + 1] = *(uint32_t*)&g23;
        }

#pragma unroll
        for (int kc = 0; kc < 4; ++kc) {
#pragma unroll
            for (int ns = 0; ns < 8; ++ns) {
                uint32_t vb0, vb1, vc0, vc1;
                uint32_t av = sb + oVh[p] + ((kc*16 + lr7 + lh8)*AT_LDB + ns*8)*2;
                uint32_t aw = sb + oVm[p] + ((kc*16 + lr7 + lh8)*AT_LDB + ns*8)*2;
                LDSM_X2T(vb0, vb1, av);
                LDSM_X2T(vc0, vc1, aw);
                MMA_BF16(oacc[ns], pfh[kc][0], pfh[kc][1], pfh[kc][2], pfh[kc][3], vb0, vb1);
                MMA_BF16(oacc[ns], pfh[kc][0], pfh[kc][1], pfh[kc][2], pfh[kc][3], vc0, vc1);
                MMA_BF16(oacc[ns], pfm[kc][0], pfm[kc][1], pfm[kc][2], pfm[kc][3], vb0, vb1);
            }
        }
        CPWAIT0();
        __syncthreads();
    }

    dr0 += __shfl_xor_sync(0xffffffffu, dr0, 1);
    dr0 += __shfl_xor_sync(0xffffffffu, dr0, 2);
    dr1 += __shfl_xor_sync(0xffffffffu, dr1, 1);
    dr1 += __shfl_xor_sync(0xffffffffu, dr1, 2);
    float i0 = 1.0f / dr0, i1 = 1.0f / dr1;

#pragma unroll
    for (int ns = 0; ns < 8; ++ns) {
        int colb = h*DH + ns*8 + (lane & 3)*2;
        {
            float w0 = oacc[ns][0]*i0, w1 = oacc[ns][1]*i0;
            size_t o = ((size_t)b*NN + r0g)*DD + colb;
            __half h0 = __float2half_rn(w0), h1 = __float2half_rn(w1);
            *(__half2*)(Aa + o) = __halves2half2(h0, h1);
            *(__half2*)(Ab + o) = __halves2half2(__float2half_rn(w0 - __half2float(h0)),
                                                 __float2half_rn(w1 - __half2float(h1)));
        }
        {
            float w0 = oacc[ns][2]*i1, w1 = oacc[ns][3]*i1;
            size_t o = ((size_t)b*NN + r1g)*DD + colb;
            __half h0 = __float2half_rn(w0), h1 = __float2half_rn(w1);
            *(__half2*)(Aa + o) = __halves2half2(h0, h1);
            *(__half2*)(Ab + o) = __halves2half2(__float2half_rn(w0 - __half2float(h0)),
                                                 __float2half_rn(w1 - __half2float(h1)));
        }
    }
}

extern "C" void kernel_launch(void* const* d_in, const int* in_sizes, int n_in,
                              void* d_out, int out_size)
{
    (void)in_sizes; (void)n_in; (void)out_size;
    const float* X  = (const float*)d_in[0];
    const float* Wq = (const float*)d_in[1];
    const float* Wk = (const float*)d_in[2];
    const float* Wv = (const float*)d_in[3];
    const float* Wo = (const float*)d_in[4];
    const float* gq = (const float*)d_in[5];
    const float* bq = (const float*)d_in[6];
    const float* gk = (const float*)d_in[7];
    const float* bk = (const float*)d_in[8];
    float* out = (float*)d_out;

    float *Yq, *Yk, *Qp, *Kp, *S0, *Fi; int* ev;
    cudaGetSymbolAddress((void**)&Yq, g_Yq);
    cudaGetSymbolAddress((void**)&Yk, g_Yk);
    cudaGetSymbolAddress((void**)&Qp, g_Q);
    cudaGetSymbolAddress((void**)&Kp, g_K);
    cudaGetSymbolAddress((void**)&S0, g_S0);
    cudaGetSymbolAddress((void**)&Fi, g_Fi);
    cudaGetSymbolAddress((void**)&ev, g_ev);
    __half *hXa,*hXb,*hWqa,*hWqb,*hWka,*hWkb,*hWva,*hWvb,*hWoa,*hWob,*hAa,*hAb;
    cudaGetSymbolAddress((void**)&hXa, g_hXa);   cudaGetSymbolAddress((void**)&hXb, g_hXb);
    cudaGetSymbolAddress((void**)&hWqa, g_hWqa); cudaGetSymbolAddress((void**)&hWqb, g_hWqb);
    cudaGetSymbolAddress((void**)&hWka, g_hWka); cudaGetSymbolAddress((void**)&hWkb, g_hWkb);
    cudaGetSymbolAddress((void**)&hWva, g_hWva); cudaGetSymbolAddress((void**)&hWvb, g_hWvb);
    cudaGetSymbolAddress((void**)&hWoa, g_hWoa); cudaGetSymbolAddress((void**)&hWob, g_hWob);
    cudaGetSymbolAddress((void**)&hAa, g_hAa);   cudaGetSymbolAddress((void**)&hAb, g_hAb);
    __nv_bfloat16 *Qh,*Qm,*Kh,*Km,*Vh,*Vm;
    cudaGetSymbolAddress((void**)&Qh, g_Qh); cudaGetSymbolAddress((void**)&Qm, g_Qm);
    cudaGetSymbolAddress((void**)&Kh, g_Kh); cudaGetSymbolAddress((void**)&Km, g_Km);
    cudaGetSymbolAddress((void**)&Vh, g_Vh); cudaGetSymbolAddress((void**)&Vm, g_Vm);

    cudaFuncSetAttribute(attn_mma_kernel, cudaFuncAttributeMaxDynamicSharedMemorySize, AT3_SMEM);
    cudaFuncSetAttribute(gemm_h2_kernel, cudaFuncAttributeMaxDynamicSharedMemorySize, GH_SMEM);

    dim3 wgrid4(32, 32, 4);
    dim3 ggrid(DD/128, RR/128);

    conv2h_kernel<<<RR*DD/1024, 256>>>(X, hXa, hXb);
    convW4_kernel<<<wgrid4, dim3(32,8)>>>(Wq, Wk, Wv, Wo,
                                          hWqa, hWqb, hWka, hWkb,
                                          hWva, hWvb, hWoa, hWob);
    gemm_h2_kernel<<<ggrid, 256, GH_SMEM>>>(hXa, hXb, hWqa, hWqb, Yq, nullptr, nullptr, 0);
    gemm_h2_kernel<<<ggrid, 256, GH_SMEM>>>(hXa, hXb, hWka, hWkb, Yk, nullptr, nullptr, 0);
    gemm_h2_kernel<<<ggrid, 256, GH_SMEM>>>(hXa, hXb, hWva, hWvb, nullptr, Vh, Vm, 1);
    ln_scatter_kernel<<<RR, 256>>>(Yq, gq, bq, Qp, Qh, Qm);
    ln_scatter_kernel<<<RR, 256>>>(Yk, gk, bk, Kp, Kh, Km);
    s0_kernel<<<dim3(MM/64, NN/64, BB), 256>>>(Qp, Kp, S0);
    finit_kernel<<<dim3(MM/64, BB), 256>>>(S0, Fi);
    scan_kernel<<<BB, 1024>>>(S0, Fi, ev);
    attn_mma_kernel<<<dim3(NN/128, HH, BB), 256, AT3_SMEM>>>(Qh, Qm, Kh, Km, Vh, Vm, ev, hAa, hAb);
    gemm_h2_kernel<<<ggrid, 256, GH_SMEM>>>(hAa, hAb, hWoa, hWob, out, nullptr, nullptr, 0);
}